// round 3
// baseline (speedup 1.0000x reference)
#include <cuda_runtime.h>
#include <cstdint>

typedef unsigned long long ull;

#define NPTS 16384
#define KCH  128
#define CG_TOTAL 3436

// ---- scratch (device globals; no runtime allocation allowed) ----
__device__ float g_m1[(size_t)NPTS * 16 * KCH];   // mixed[1]
__device__ float g_m2[(size_t)NPTS * 16 * KCH];   // mixed[2]
__device__ float g_tp[(size_t)NPTS * 16 * KCH];   // tensor-product result
__device__ ull   g_cgdup[CG_TOTAL];               // compacted cg, each coeff duplicated (c,c)

// ---- packed f32x2 helpers (sm_100a) ----
__device__ __forceinline__ ull dup2(float x) {
    ull r; asm("mov.b64 %0, {%1, %1};" : "=l"(r) : "f"(x)); return r;
}
__device__ __forceinline__ void ffma2(ull& d, ull a, ull b) {
    asm("fma.rn.f32x2 %0, %1, %2, %0;" : "+l"(d) : "l"(a), "l"(b));
}
__device__ __forceinline__ ull fmul2(ull a, ull b) {
    ull d; asm("mul.rn.f32x2 %0, %1, %2;" : "=l"(d) : "l"(a), "l"(b)); return d;
}
__device__ __forceinline__ ull fadd2(ull a, ull b) {
    ull d; asm("add.rn.f32x2 %0, %1, %2;" : "=l"(d) : "l"(a), "l"(b)); return d;
}

// ============================================================================
// prep: compact the (4,4,4,7,7,7) cg tensor into path order, duplicating each
// coefficient into an 8-byte (c,c) pair. Order MUST match tp_kernel's walk:
// l2 -> l1 -> i -> j -> l(valid) -> m
// ============================================================================
__global__ void prep_cg_kernel(const float* __restrict__ cg) {
    int idx = blockIdx.x * blockDim.x + threadIdx.x;
    if (idx >= CG_TOTAL) return;
    int off = 0;
    for (int l2 = 0; l2 < 4; l2++) {
        int d2 = 2 * l2 + 1;
        for (int l1 = 0; l1 < 4; l1++) {
            int d1 = 2 * l1 + 1;
            for (int i = 0; i < d1; i++)
                for (int j = 0; j < d2; j++)
                    for (int l = 0; l < 4; l++) {
                        int lo = (l1 > l2) ? (l1 - l2) : (l2 - l1);
                        if (l < lo || l > l1 + l2) continue;
                        int dl = 2 * l + 1;
                        for (int m = 0; m < dl; m++) {
                            if (off == idx) {
                                float c = cg[((((l1 * 4 + l2) * 4 + l) * 7 + i) * 7 + j) * 7 + m];
                                g_cgdup[idx] = dup2(c);
                                return;
                            }
                            off++;
                        }
                    }
        }
    }
}

// ============================================================================
// GEMM: C[M,128] = A[M,128] @ W[128,128]  (optionally C += ...)
// 128x128 block tile, 256 threads, per-thread 8 rows x 4 col-pairs, f32x2 FMA.
// ============================================================================
__global__ __launch_bounds__(256, 2) void gemm_kernel(
    const float* __restrict__ A, const float* __restrict__ W,
    float* __restrict__ C, int accum)
{
    __shared__ float As[128][32];   // [row][k]   16 KB
    __shared__ float Bs[32][128];   // [k][q]     16 KB

    const int tid = threadIdx.x;
    const int tx = tid & 15;        // col group (8 cols each)
    const int ty = tid >> 4;        // row group (8 rows each)
    const int rowBase = blockIdx.x << 7;

    ull acc[8][4];
#pragma unroll
    for (int r = 0; r < 8; r++)
#pragma unroll
        for (int p = 0; p < 4; p++) acc[r][p] = 0ull;

    for (int kc = 0; kc < 128; kc += 32) {
        // load A chunk: 128 rows x 32 k  (1024 float4, 4 per thread)
#pragma unroll
        for (int i = 0; i < 4; i++) {
            int idx = tid + (i << 8);
            int r = idx >> 3, kk = (idx & 7) << 2;
            *(float4*)&As[r][kk] = *(const float4*)&A[(rowBase + r) * 128 + kc + kk];
        }
        // load B chunk: 32 k x 128 q
#pragma unroll
        for (int i = 0; i < 4; i++) {
            int idx = tid + (i << 8);
            int kr = idx >> 5, q4 = (idx & 31) << 2;
            *(float4*)&Bs[kr][q4] = *(const float4*)&W[(kc + kr) * 128 + q4];
        }
        __syncthreads();
#pragma unroll
        for (int k = 0; k < 32; k++) {
            ull b[4];
            const ull* bp = (const ull*)&Bs[k][tx << 3];
            b[0] = bp[0]; b[1] = bp[1]; b[2] = bp[2]; b[3] = bp[3];
#pragma unroll
            for (int r = 0; r < 8; r++) {
                ull av = dup2(As[(ty << 3) + r][k]);
                ffma2(acc[r][0], av, b[0]);
                ffma2(acc[r][1], av, b[1]);
                ffma2(acc[r][2], av, b[2]);
                ffma2(acc[r][3], av, b[3]);
            }
        }
        __syncthreads();
    }

    // epilogue
#pragma unroll
    for (int r = 0; r < 8; r++) {
        float* crow = &C[(rowBase + (ty << 3) + r) * 128 + (tx << 3)];
#pragma unroll
        for (int p = 0; p < 4; p++) {
            ull v = acc[r][p];
            if (accum) v = fadd2(v, *(const ull*)&crow[p << 1]);
            *(ull*)&crow[p << 1] = v;
        }
    }
}

// ============================================================================
// Tensor product: out[n,(l,m),k] = sum_{l1,l2 valid} cg[i,j,m] a[n,(l1,i),k] b[n,(l2,j),k]
// One thread per (n, 4-channel group). 3436 coefficients fully unrolled,
// each coeff: 1 broadcast LDS.64 + 2 FFMA2 (4 FMAs).
// ============================================================================
__global__ __launch_bounds__(256) void tp_kernel(
    const float* __restrict__ aBase, const float* __restrict__ bBase,
    float* __restrict__ oBase)
{
    __shared__ ull s_cg[CG_TOTAL];
    for (int i = threadIdx.x; i < CG_TOTAL; i += 256) s_cg[i] = g_cgdup[i];
    __syncthreads();

    const int gid = blockIdx.x * 256 + threadIdx.x;
    const int kq = (gid & 31) << 2;       // channel offset (floats)
    const int n  = gid >> 5;

    constexpr int CUM[4] = {0, 1, 4, 9};                       // cumulative degree
    constexpr int OFFL[4] = {0, 1 * NPTS * KCH, 4 * NPTS * KCH, 9 * NPTS * KCH};

    // load a (current): 16 rows x 4 channels
    ull a[16][2];
#pragma unroll
    for (int l1 = 0; l1 < 4; l1++) {
        const int d1 = 2 * l1 + 1;
#pragma unroll
        for (int i = 0; i < d1; i++) {
            ulonglong2 v = *(const ulonglong2*)(aBase + OFFL[l1] + (n * d1 + i) * KCH + kq);
            a[CUM[l1] + i][0] = v.x; a[CUM[l1] + i][1] = v.y;
        }
    }

    ull acc[16][2];
#pragma unroll
    for (int r = 0; r < 16; r++) { acc[r][0] = 0ull; acc[r][1] = 0ull; }

    int cgi = 0;
#pragma unroll
    for (int l2 = 0; l2 < 4; l2++) {
        const int d2 = 2 * l2 + 1;
        ull b[7][2];
#pragma unroll
        for (int j = 0; j < d2; j++) {
            ulonglong2 v = *(const ulonglong2*)(bBase + OFFL[l2] + (n * d2 + j) * KCH + kq);
            b[j][0] = v.x; b[j][1] = v.y;
        }
#pragma unroll
        for (int l1 = 0; l1 < 4; l1++) {
            const int d1 = 2 * l1 + 1;
#pragma unroll
            for (int i = 0; i < d1; i++) {
#pragma unroll
                for (int j = 0; j < d2; j++) {
                    ull p0 = fmul2(a[CUM[l1] + i][0], b[j][0]);
                    ull p1 = fmul2(a[CUM[l1] + i][1], b[j][1]);
#pragma unroll
                    for (int l = 0; l < 4; l++) {
                        const int lo = (l1 > l2) ? (l1 - l2) : (l2 - l1);
                        if (l < lo || l > l1 + l2) continue;
                        const int dl = 2 * l + 1;
#pragma unroll
                        for (int m = 0; m < dl; m++) {
                            ull c = s_cg[cgi];
                            cgi++;
                            ffma2(acc[CUM[l] + m][0], c, p0);
                            ffma2(acc[CUM[l] + m][1], c, p1);
                        }
                    }
                }
            }
        }
    }

    // store
#pragma unroll
    for (int l = 0; l < 4; l++) {
        const int dl = 2 * l + 1;
#pragma unroll
        for (int m = 0; m < dl; m++) {
            ulonglong2 v;
            v.x = acc[CUM[l] + m][0]; v.y = acc[CUM[l] + m][1];
            *(ulonglong2*)(oBase + OFFL[l] + (n * dl + m) * KCH + kq) = v;
        }
    }
}

// ============================================================================
// launch
// ============================================================================
extern "C" void kernel_launch(void* const* d_in, const int* in_sizes, int n_in,
                              void* d_out, int out_size)
{
    const float* f[4] = {nullptr, nullptr, nullptr, nullptr};
    const float* mixer = nullptr;
    const float* iterw = nullptr;
    const float* cg = nullptr;

    for (int i = 0; i < n_in; i++) {
        const float* p = (const float*)d_in[i];
        switch (in_sizes[i]) {
            case 2097152:  f[0] = p; break;   // 16384*1*128
            case 6291456:  f[1] = p; break;   // 16384*3*128
            case 10485760: f[2] = p; break;   // 16384*5*128
            case 14680064: f[3] = p; break;   // 16384*7*128
            case 196608:   mixer = p; break;  // 3*4*128*128
            case 131072:   iterw = p; break;  // 2*4*128*128
            case 21952:    cg = p; break;     // 4*4*4*7*7*7
        }
    }
    // positional fallback
    if (!f[0] || !f[1] || !f[2] || !f[3] || !mixer || !iterw || !cg) {
        f[0] = (const float*)d_in[0]; f[1] = (const float*)d_in[1];
        f[2] = (const float*)d_in[2]; f[3] = (const float*)d_in[3];
        mixer = (const float*)d_in[4]; iterw = (const float*)d_in[5];
        cg = (const float*)d_in[6];
    }

    float* out = (float*)d_out;
    float *m1, *m2, *tpb;
    cudaGetSymbolAddress((void**)&m1, g_m1);
    cudaGetSymbolAddress((void**)&m2, g_m2);
    cudaGetSymbolAddress((void**)&tpb, g_tp);

    const size_t OFFL[4] = {0, (size_t)1 * NPTS * KCH, (size_t)4 * NPTS * KCH, (size_t)9 * NPTS * KCH};
    const int MB[4] = {NPTS * 1 / 128, NPTS * 3 / 128, NPTS * 5 / 128, NPTS * 7 / 128};

    prep_cg_kernel<<<(CG_TOTAL + 255) / 256, 256>>>(cg);

    // mixed[i] = density @ mixer_w[i];  mixed[0] -> d_out (becomes `current`)
    float* dst[3] = {out, m1, m2};
    for (int i = 0; i < 3; i++)
        for (int l = 0; l < 4; l++)
            gemm_kernel<<<MB[l], 256>>>(f[l], mixer + (size_t)(i * 4 + l) * 128 * 128,
                                        dst[i] + OFFL[l], 0);

    // iteration 0: tp = TP(current, mixed1); current += tp @ iter_w[0]
    tp_kernel<<<NPTS * 32 / 256, 256>>>(out, m1, tpb);
    for (int l = 0; l < 4; l++)
        gemm_kernel<<<MB[l], 256>>>(tpb + OFFL[l], iterw + (size_t)(0 * 4 + l) * 128 * 128,
                                    out + OFFL[l], 1);

    // iteration 1: tp = TP(current, mixed2); current += tp @ iter_w[1]
    tp_kernel<<<NPTS * 32 / 256, 256>>>(out, m2, tpb);
    for (int l = 0; l < 4; l++)
        gemm_kernel<<<MB[l], 256>>>(tpb + OFFL[l], iterw + (size_t)(1 * 4 + l) * 128 * 128,
                                    out + OFFL[l], 1);
}

// round 5
// speedup vs baseline: 1.2632x; 1.2632x over previous
#include <cuda_runtime.h>
#include <cuda_bf16.h>
#include <cstdint>

typedef unsigned long long ull;

#define NPTS 16384
#define KCH  128
#define CG_TOTAL 3436
#define NW 20                      // 12 mixer + 8 iter weight matrices

// ---- scratch (device globals; no runtime allocation allowed) ----
__device__ float g_m1[(size_t)NPTS * 16 * KCH];   // mixed[1]
__device__ float g_m2[(size_t)NPTS * 16 * KCH];   // mixed[2]
__device__ float g_tp[(size_t)NPTS * 16 * KCH];   // tensor-product result
__device__ ull   g_cgdup[CG_TOTAL];               // compacted cg, duplicated (c,c)
__device__ __nv_bfloat16 g_wthi[(size_t)NW * 128 * 128];  // W^T hi split, [w][q][k]
__device__ __nv_bfloat16 g_wtlo[(size_t)NW * 128 * 128];  // W^T lo split

// ---- packed f32x2 helpers ----
__device__ __forceinline__ ull dup2(float x) {
    ull r; asm("mov.b64 %0, {%1, %1};" : "=l"(r) : "f"(x)); return r;
}
__device__ __forceinline__ void ffma2(ull& d, ull a, ull b) {
    asm("fma.rn.f32x2 %0, %1, %2, %0;" : "+l"(d) : "l"(a), "l"(b));
}
__device__ __forceinline__ ull fmul2(ull a, ull b) {
    ull d; asm("mul.rn.f32x2 %0, %1, %2;" : "=l"(d) : "l"(a), "l"(b)); return d;
}

// ---- sm_80-compatible tensor-core primitives ----
__device__ __forceinline__ uint32_t smem_u32(const void* p) {
    uint32_t a;
    asm("{ .reg .u64 t; cvta.to.shared.u64 t, %1; cvt.u32.u64 %0, t; }" : "=r"(a) : "l"(p));
    return a;
}
__device__ __forceinline__ void ldsm4(uint32_t* r, uint32_t a) {
    asm volatile("ldmatrix.sync.aligned.m8n8.x4.shared.b16 {%0,%1,%2,%3}, [%4];"
        : "=r"(r[0]), "=r"(r[1]), "=r"(r[2]), "=r"(r[3]) : "r"(a));
}
__device__ __forceinline__ void ldsm2(uint32_t* r, uint32_t a) {
    asm volatile("ldmatrix.sync.aligned.m8n8.x2.shared.b16 {%0,%1}, [%2];"
        : "=r"(r[0]), "=r"(r[1]) : "r"(a));
}
__device__ __forceinline__ void mma_bf16(float* c, const uint32_t* a, const uint32_t* b) {
    asm volatile("mma.sync.aligned.m16n8k16.row.col.f32.bf16.bf16.f32 "
        "{%0,%1,%2,%3}, {%4,%5,%6,%7}, {%8,%9}, {%0,%1,%2,%3};"
        : "+f"(c[0]), "+f"(c[1]), "+f"(c[2]), "+f"(c[3])
        : "r"(a[0]), "r"(a[1]), "r"(a[2]), "r"(a[3]), "r"(b[0]), "r"(b[1]));
}

// bf16 split: v = hi + lo  (hi = rn(v), lo = rn(v - hi))
__device__ __forceinline__ void split_bf16(float v, unsigned short& h, unsigned short& l) {
    __nv_bfloat16 hb = __float2bfloat16(v);
    float r = v - __bfloat162float(hb);
    __nv_bfloat16 lb = __float2bfloat16(r);
    h = __bfloat16_as_ushort(hb);
    l = __bfloat16_as_ushort(lb);
}
__device__ __forceinline__ uint32_t pack16(unsigned short a, unsigned short b) {
    return (uint32_t)a | ((uint32_t)b << 16);
}

// ============================================================================
// prep: compact cg into path order (l2 -> l1 -> i -> j -> l -> m), dup (c,c)
// ============================================================================
__global__ void prep_cg_kernel(const float* __restrict__ cg) {
    int idx = blockIdx.x * blockDim.x + threadIdx.x;
    if (idx >= CG_TOTAL) return;
    int off = 0;
    for (int l2 = 0; l2 < 4; l2++) {
        int d2 = 2 * l2 + 1;
        for (int l1 = 0; l1 < 4; l1++) {
            int d1 = 2 * l1 + 1;
            for (int i = 0; i < d1; i++)
                for (int j = 0; j < d2; j++)
                    for (int l = 0; l < 4; l++) {
                        int lo = (l1 > l2) ? (l1 - l2) : (l2 - l1);
                        if (l < lo || l > l1 + l2) continue;
                        int dl = 2 * l + 1;
                        for (int m = 0; m < dl; m++) {
                            if (off == idx) {
                                float c = cg[((((l1 * 4 + l2) * 4 + l) * 7 + i) * 7 + j) * 7 + m];
                                g_cgdup[idx] = dup2(c);
                                return;
                            }
                            off++;
                        }
                    }
        }
    }
}

// ============================================================================
// prep: transpose + bf16-split all 20 weight matrices once.
// Wt[w][q][k] = split(W[w][k][q])
// ============================================================================
__global__ void prep_w_kernel(const float* __restrict__ mixer, const float* __restrict__ iterw) {
    int b = blockIdx.x;
    const float* W = (b < 12) ? (mixer + (size_t)b * 16384) : (iterw + (size_t)(b - 12) * 16384);
    __nv_bfloat16* hi = g_wthi + (size_t)b * 16384;
    __nv_bfloat16* lo = g_wtlo + (size_t)b * 16384;
    for (int idx = threadIdx.x; idx < 16384; idx += 256) {
        int q = idx & 127, k = idx >> 7;       // read W[k][q] contiguous in q
        float v = W[idx];
        unsigned short h, l;
        split_bf16(v, h, l);
        hi[q * 128 + k] = __ushort_as_bfloat16(h);
        lo[q * 128 + k] = __ushort_as_bfloat16(l);
    }
}

// ============================================================================
// Tensor-core GEMM (HMMA mma.sync): C[tile 128,128] = A @ W (+C)
// Double-bf16 split, fp32 accum. Smem rows padded to 272B (17x16B) so
// ldmatrix 8-row address sets are bank-conflict-free.
// ============================================================================
#define RS 272                     // padded row stride (bytes)
#define T_BYTES (128 * RS)         // 34816 per tile
#define A_HI 0
#define A_LO (1 * T_BYTES)
#define W_HI (2 * T_BYTES)
#define W_LO (3 * T_BYTES)
#define GEMM_SMEM (4 * T_BYTES)    // 139264 B

__global__ __launch_bounds__(256, 1) void tc_gemm(
    const float* __restrict__ A,
    const __nv_bfloat16* __restrict__ wthi,
    const __nv_bfloat16* __restrict__ wtlo,
    float* __restrict__ C, int accum)
{
    extern __shared__ char smem[];
    const int tid = threadIdx.x;
    const int wid = tid >> 5;
    const int lane = tid & 31;
    const int rowBase = blockIdx.x << 7;

    // ---- stage W^T hi/lo into padded smem (coalesced 16B copies) ----
    // 2048 16B units per tile
    for (int u = tid; u < 2048; u += 256) {
        int r = u >> 4, c = u & 15;
        *(uint4*)(smem + W_HI + r * RS + c * 16) = *(const uint4*)((const char*)wthi + r * 256 + c * 16);
        *(uint4*)(smem + W_LO + r * RS + c * 16) = *(const uint4*)((const char*)wtlo + r * 256 + c * 16);
    }

    // ---- convert A tile to bf16 hi/lo in padded smem ----
    // 128 rows x 32 float4 = 4096 units; 16 per thread
#pragma unroll
    for (int it = 0; it < 16; it++) {
        int idx = tid + (it << 8);
        int row = idx >> 5;
        int kq = (idx & 31) << 2;
        float4 v = *(const float4*)(A + (size_t)(rowBase + row) * 128 + kq);
        unsigned short h0, l0, h1, l1, h2, l2, h3, l3;
        split_bf16(v.x, h0, l0); split_bf16(v.y, h1, l1);
        split_bf16(v.z, h2, l2); split_bf16(v.w, h3, l3);
        uint32_t hlo = pack16(h0, h1), hhi = pack16(h2, h3);
        uint32_t llo = pack16(l0, l1), lhi = pack16(l2, l3);
        ull hv = (ull)hlo | ((ull)hhi << 32);
        ull lv = (ull)llo | ((ull)lhi << 32);
        *(ull*)(smem + A_HI + row * RS + kq * 2) = hv;
        *(ull*)(smem + A_LO + row * RS + kq * 2) = lv;
    }
    __syncthreads();

    const uint32_t sb = smem_u32(smem);
    const int warpM = (wid >> 1) << 5;   // 0,32,64,96
    const int warpN = (wid & 1) << 6;    // 0,64

    float acc[2][8][4];
#pragma unroll
    for (int mt = 0; mt < 2; mt++)
#pragma unroll
        for (int nt = 0; nt < 8; nt++)
#pragma unroll
            for (int i = 0; i < 4; i++) acc[mt][nt][i] = 0.0f;

    // ldmatrix per-lane addressing
    const int aRow = lane & 15;
    const uint32_t aK = (lane & 16) ? 16 : 0;     // byte offset for k8-15 matrices
    const int bRow = lane & 7;
    const uint32_t bK = (lane & 8) ? 16 : 0;

#pragma unroll
    for (int kc = 0; kc < 8; kc++) {
        const uint32_t kb = kc * 32;              // k0*2 bytes
        uint32_t a_hi[2][4], a_lo[2][4];
#pragma unroll
        for (int mt = 0; mt < 2; mt++) {
            uint32_t off = (uint32_t)((warpM + mt * 16 + aRow) * RS) + kb + aK;
            ldsm4(a_hi[mt], sb + A_HI + off);
            ldsm4(a_lo[mt], sb + A_LO + off);
        }
#pragma unroll
        for (int nt = 0; nt < 8; nt++) {
            uint32_t off = (uint32_t)((warpN + nt * 8 + bRow) * RS) + kb + bK;
            uint32_t bh[2], bl[2];
            ldsm2(bh, sb + W_HI + off);
            ldsm2(bl, sb + W_LO + off);
#pragma unroll
            for (int mt = 0; mt < 2; mt++) {
                mma_bf16(acc[mt][nt], a_hi[mt], bh);
                mma_bf16(acc[mt][nt], a_hi[mt], bl);
                mma_bf16(acc[mt][nt], a_lo[mt], bh);
            }
        }
    }

    // ---- epilogue ----
    const int mrow = lane >> 2;
    const int ncol = (lane & 3) << 1;
#pragma unroll
    for (int mt = 0; mt < 2; mt++) {
#pragma unroll
        for (int nt = 0; nt < 8; nt++) {
            int row0 = rowBase + warpM + mt * 16 + mrow;
            int col = warpN + nt * 8 + ncol;
            float2* p0 = (float2*)(C + (size_t)row0 * 128 + col);
            float2* p1 = (float2*)(C + (size_t)(row0 + 8) * 128 + col);
            float2 v0 = make_float2(acc[mt][nt][0], acc[mt][nt][1]);
            float2 v1 = make_float2(acc[mt][nt][2], acc[mt][nt][3]);
            if (accum) {
                float2 c0 = *p0, c1 = *p1;
                v0.x += c0.x; v0.y += c0.y;
                v1.x += c1.x; v1.y += c1.y;
            }
            *p0 = v0;
            *p1 = v1;
        }
    }
}

// ============================================================================
// Tensor product (unchanged): thread per (n, 4-ch group), f32x2 FMA.
// ============================================================================
__global__ __launch_bounds__(256) void tp_kernel(
    const float* __restrict__ aBase, const float* __restrict__ bBase,
    float* __restrict__ oBase)
{
    __shared__ ull s_cg[CG_TOTAL];
    for (int i = threadIdx.x; i < CG_TOTAL; i += 256) s_cg[i] = g_cgdup[i];
    __syncthreads();

    const int gid = blockIdx.x * 256 + threadIdx.x;
    const int kq = (gid & 31) << 2;
    const int n  = gid >> 5;

    constexpr int CUM[4] = {0, 1, 4, 9};
    constexpr int OFFL[4] = {0, 1 * NPTS * KCH, 4 * NPTS * KCH, 9 * NPTS * KCH};

    ull a[16][2];
#pragma unroll
    for (int l1 = 0; l1 < 4; l1++) {
        const int d1 = 2 * l1 + 1;
#pragma unroll
        for (int i = 0; i < d1; i++) {
            ulonglong2 v = *(const ulonglong2*)(aBase + OFFL[l1] + (n * d1 + i) * KCH + kq);
            a[CUM[l1] + i][0] = v.x; a[CUM[l1] + i][1] = v.y;
        }
    }

    ull acc[16][2];
#pragma unroll
    for (int r = 0; r < 16; r++) { acc[r][0] = 0ull; acc[r][1] = 0ull; }

    int cgi = 0;
#pragma unroll
    for (int l2 = 0; l2 < 4; l2++) {
        const int d2 = 2 * l2 + 1;
        ull b[7][2];
#pragma unroll
        for (int j = 0; j < d2; j++) {
            ulonglong2 v = *(const ulonglong2*)(bBase + OFFL[l2] + (n * d2 + j) * KCH + kq);
            b[j][0] = v.x; b[j][1] = v.y;
        }
#pragma unroll
        for (int l1 = 0; l1 < 4; l1++) {
            const int d1 = 2 * l1 + 1;
#pragma unroll
            for (int i = 0; i < d1; i++) {
#pragma unroll
                for (int j = 0; j < d2; j++) {
                    ull p0 = fmul2(a[CUM[l1] + i][0], b[j][0]);
                    ull p1 = fmul2(a[CUM[l1] + i][1], b[j][1]);
#pragma unroll
                    for (int l = 0; l < 4; l++) {
                        const int lo = (l1 > l2) ? (l1 - l2) : (l2 - l1);
                        if (l < lo || l > l1 + l2) continue;
                        const int dl = 2 * l + 1;
#pragma unroll
                        for (int m = 0; m < dl; m++) {
                            ull c = s_cg[cgi];
                            cgi++;
                            ffma2(acc[CUM[l] + m][0], c, p0);
                            ffma2(acc[CUM[l] + m][1], c, p1);
                        }
                    }
                }
            }
        }
    }

#pragma unroll
    for (int l = 0; l < 4; l++) {
        const int dl = 2 * l + 1;
#pragma unroll
        for (int m = 0; m < dl; m++) {
            ulonglong2 v;
            v.x = acc[CUM[l] + m][0]; v.y = acc[CUM[l] + m][1];
            *(ulonglong2*)(oBase + OFFL[l] + (n * dl + m) * KCH + kq) = v;
        }
    }
}

// ============================================================================
// launch
// ============================================================================
extern "C" void kernel_launch(void* const* d_in, const int* in_sizes, int n_in,
                              void* d_out, int out_size)
{
    const float* f[4] = {nullptr, nullptr, nullptr, nullptr};
    const float* mixer = nullptr;
    const float* iterw = nullptr;
    const float* cg = nullptr;

    for (int i = 0; i < n_in; i++) {
        const float* p = (const float*)d_in[i];
        switch (in_sizes[i]) {
            case 2097152:  f[0] = p; break;
            case 6291456:  f[1] = p; break;
            case 10485760: f[2] = p; break;
            case 14680064: f[3] = p; break;
            case 196608:   mixer = p; break;
            case 131072:   iterw = p; break;
            case 21952:    cg = p; break;
        }
    }
    if (!f[0] || !f[1] || !f[2] || !f[3] || !mixer || !iterw || !cg) {
        f[0] = (const float*)d_in[0]; f[1] = (const float*)d_in[1];
        f[2] = (const float*)d_in[2]; f[3] = (const float*)d_in[3];
        mixer = (const float*)d_in[4]; iterw = (const float*)d_in[5];
        cg = (const float*)d_in[6];
    }

    cudaFuncSetAttribute(tc_gemm, cudaFuncAttributeMaxDynamicSharedMemorySize, GEMM_SMEM);

    float* out = (float*)d_out;
    float *m1, *m2, *tpb;
    __nv_bfloat16 *whi, *wlo;
    cudaGetSymbolAddress((void**)&m1, g_m1);
    cudaGetSymbolAddress((void**)&m2, g_m2);
    cudaGetSymbolAddress((void**)&tpb, g_tp);
    cudaGetSymbolAddress((void**)&whi, g_wthi);
    cudaGetSymbolAddress((void**)&wlo, g_wtlo);

    const size_t OFFL[4] = {0, (size_t)1 * NPTS * KCH, (size_t)4 * NPTS * KCH, (size_t)9 * NPTS * KCH};
    const int MB[4] = {NPTS * 1 / 128, NPTS * 3 / 128, NPTS * 5 / 128, NPTS * 7 / 128};

    prep_cg_kernel<<<(CG_TOTAL + 255) / 256, 256>>>(cg);
    prep_w_kernel<<<NW, 256>>>(mixer, iterw);

    // mixed[i] = density @ mixer_w[i]; mixed[0] -> d_out (becomes `current`)
    float* dst[3] = {out, m1, m2};
    for (int i = 0; i < 3; i++)
        for (int l = 0; l < 4; l++) {
            int w = i * 4 + l;
            tc_gemm<<<MB[l], 256, GEMM_SMEM>>>(f[l], whi + (size_t)w * 16384,
                                               wlo + (size_t)w * 16384, dst[i] + OFFL[l], 0);
        }

    // iteration 0: tp = TP(current, mixed1); current += tp @ iter_w[0]
    tp_kernel<<<NPTS * 32 / 256, 256>>>(out, m1, tpb);
    for (int l = 0; l < 4; l++) {
        int w = 12 + 0 * 4 + l;
        tc_gemm<<<MB[l], 256, GEMM_SMEM>>>(tpb + OFFL[l], whi + (size_t)w * 16384,
                                           wlo + (size_t)w * 16384, out + OFFL[l], 1);
    }

    // iteration 1: tp = TP(current, mixed2); current += tp @ iter_w[1]
    tp_kernel<<<NPTS * 32 / 256, 256>>>(out, m2, tpb);
    for (int l = 0; l < 4; l++) {
        int w = 12 + 1 * 4 + l;
        tc_gemm<<<MB[l], 256, GEMM_SMEM>>>(tpb + OFFL[l], whi + (size_t)w * 16384,
                                           wlo + (size_t)w * 16384, out + OFFL[l], 1);
    }
}

// round 6
// speedup vs baseline: 1.3969x; 1.1059x over previous
#include <cuda_runtime.h>
#include <cuda_bf16.h>
#include <cstdint>

typedef unsigned long long ull;

#define NPTS 16384
#define KCH  128
#define CG_TOTAL 3436
#define NW 20                      // 12 mixer + 8 iter weight matrices

// ---- scratch (device globals; no runtime allocation allowed) ----
__device__ float g_m1[(size_t)NPTS * 16 * KCH];   // mixed[1]
__device__ float g_m2[(size_t)NPTS * 16 * KCH];   // mixed[2]
__device__ float g_tp[(size_t)NPTS * 16 * KCH];   // tensor-product result
__device__ ull   g_cgdup[CG_TOTAL];               // compacted cg, duplicated (c,c)
__device__ __nv_bfloat16 g_wthi[(size_t)NW * 128 * 128];  // W^T hi split, [w][q][k]
__device__ __nv_bfloat16 g_wtlo[(size_t)NW * 128 * 128];  // W^T lo split

// ---- packed f32x2 helpers ----
__device__ __forceinline__ ull dup2(float x) {
    ull r; asm("mov.b64 %0, {%1, %1};" : "=l"(r) : "f"(x)); return r;
}
__device__ __forceinline__ void ffma2(ull& d, ull a, ull b) {
    asm("fma.rn.f32x2 %0, %1, %2, %0;" : "+l"(d) : "l"(a), "l"(b));
}
__device__ __forceinline__ ull fmul2(ull a, ull b) {
    ull d; asm("mul.rn.f32x2 %0, %1, %2;" : "=l"(d) : "l"(a), "l"(b)); return d;
}

// ---- sm_80-compatible tensor-core primitives ----
__device__ __forceinline__ uint32_t smem_u32(const void* p) {
    uint32_t a;
    asm("{ .reg .u64 t; cvta.to.shared.u64 t, %1; cvt.u32.u64 %0, t; }" : "=r"(a) : "l"(p));
    return a;
}
__device__ __forceinline__ void ldsm4(uint32_t* r, uint32_t a) {
    asm volatile("ldmatrix.sync.aligned.m8n8.x4.shared.b16 {%0,%1,%2,%3}, [%4];"
        : "=r"(r[0]), "=r"(r[1]), "=r"(r[2]), "=r"(r[3]) : "r"(a));
}
__device__ __forceinline__ void ldsm2(uint32_t* r, uint32_t a) {
    asm volatile("ldmatrix.sync.aligned.m8n8.x2.shared.b16 {%0,%1}, [%2];"
        : "=r"(r[0]), "=r"(r[1]) : "r"(a));
}
__device__ __forceinline__ void mma_bf16(float* c, const uint32_t* a, const uint32_t* b) {
    asm volatile("mma.sync.aligned.m16n8k16.row.col.f32.bf16.bf16.f32 "
        "{%0,%1,%2,%3}, {%4,%5,%6,%7}, {%8,%9}, {%0,%1,%2,%3};"
        : "+f"(c[0]), "+f"(c[1]), "+f"(c[2]), "+f"(c[3])
        : "r"(a[0]), "r"(a[1]), "r"(a[2]), "r"(a[3]), "r"(b[0]), "r"(b[1]));
}

// bf16 split: v = hi + lo  (hi = rn(v), lo = rn(v - hi))
__device__ __forceinline__ void split_bf16(float v, unsigned short& h, unsigned short& l) {
    __nv_bfloat16 hb = __float2bfloat16(v);
    float r = v - __bfloat162float(hb);
    __nv_bfloat16 lb = __float2bfloat16(r);
    h = __bfloat16_as_ushort(hb);
    l = __bfloat16_as_ushort(lb);
}
__device__ __forceinline__ uint32_t pack16(unsigned short a, unsigned short b) {
    return (uint32_t)a | ((uint32_t)b << 16);
}

// ============================================================================
// prep: compact cg into path order (l2 -> l1 -> i -> j -> l -> m), dup (c,c)
// ============================================================================
__global__ void prep_cg_kernel(const float* __restrict__ cg) {
    int idx = blockIdx.x * blockDim.x + threadIdx.x;
    if (idx >= CG_TOTAL) return;
    int off = 0;
    for (int l2 = 0; l2 < 4; l2++) {
        int d2 = 2 * l2 + 1;
        for (int l1 = 0; l1 < 4; l1++) {
            int d1 = 2 * l1 + 1;
            for (int i = 0; i < d1; i++)
                for (int j = 0; j < d2; j++)
                    for (int l = 0; l < 4; l++) {
                        int lo = (l1 > l2) ? (l1 - l2) : (l2 - l1);
                        if (l < lo || l > l1 + l2) continue;
                        int dl = 2 * l + 1;
                        for (int m = 0; m < dl; m++) {
                            if (off == idx) {
                                float c = cg[((((l1 * 4 + l2) * 4 + l) * 7 + i) * 7 + j) * 7 + m];
                                g_cgdup[idx] = dup2(c);
                                return;
                            }
                            off++;
                        }
                    }
        }
    }
}

// ============================================================================
// prep: transpose + bf16-split all 20 weight matrices once.
// ============================================================================
__global__ void prep_w_kernel(const float* __restrict__ mixer, const float* __restrict__ iterw) {
    int b = blockIdx.x;
    const float* W = (b < 12) ? (mixer + (size_t)b * 16384) : (iterw + (size_t)(b - 12) * 16384);
    __nv_bfloat16* hi = g_wthi + (size_t)b * 16384;
    __nv_bfloat16* lo = g_wtlo + (size_t)b * 16384;
    for (int idx = threadIdx.x; idx < 16384; idx += 256) {
        int q = idx & 127, k = idx >> 7;
        float v = W[idx];
        unsigned short h, l;
        split_bf16(v, h, l);
        hi[q * 128 + k] = __ushort_as_bfloat16(h);
        lo[q * 128 + k] = __ushort_as_bfloat16(l);
    }
}

// ============================================================================
// Fused stage GEMM (HMMA): M-tile=64, 2 CTAs/SM, all l / all dsts in one grid.
// C[64,128] = A[64,128] @ W^T[128,128] (double-bf16: hh + hl + lh), +C optional.
// gridDim.x = nStages * 4096; tile cum per l (M=64): {0,256,1024,2304,4096}.
// ============================================================================
#define RS 272                       // padded row stride (bytes), 256 data + 16
#define A_T (64 * RS)                // 17408
#define A_HI 0
#define A_LO A_T
#define W_HI (2 * A_T)
#define W_LO (2 * A_T + 128 * RS)
#define GEMM_SMEM (2 * A_T + 2 * 128 * RS)   // 104448 B

__global__ __launch_bounds__(256, 2) void tc_gemm_stage(
    const float* __restrict__ s0, const float* __restrict__ s1,
    const float* __restrict__ s2, const float* __restrict__ s3,
    float* __restrict__ d0, float* __restrict__ d1, float* __restrict__ d2,
    const __nv_bfloat16* __restrict__ whiB, const __nv_bfloat16* __restrict__ wloB,
    int wbase, int accum)
{
    extern __shared__ char smem[];
    const int tid = threadIdx.x;
    const int wid = tid >> 5;
    const int lane = tid & 31;

    // ---- decode block -> (stage, l, tile) ----
    const int bid = blockIdx.x;
    const int stage = bid >> 12;
    const int t = bid & 4095;
    int l, tcum;
    if (t >= 2304)      { l = 3; tcum = 2304; }
    else if (t >= 1024) { l = 2; tcum = 1024; }
    else if (t >= 256)  { l = 1; tcum = 256; }
    else                { l = 0; tcum = 0; }
    const int tileInL = t - tcum;

    const float* srcL = (l == 0) ? s0 : (l == 1) ? s1 : (l == 2) ? s2 : s3;
    float* dstS = (stage == 0) ? d0 : (stage == 1) ? d1 : d2;
    const size_t OFFL[4] = {0, (size_t)1 * NPTS * KCH, (size_t)4 * NPTS * KCH, (size_t)9 * NPTS * KCH};
    const float* A = srcL + (size_t)tileInL * 64 * 128;
    float* C = dstS + OFFL[l] + (size_t)tileInL * 64 * 128;
    const int w = wbase + stage * 4 + l;
    const __nv_bfloat16* wthi = whiB + (size_t)w * 16384;
    const __nv_bfloat16* wtlo = wloB + (size_t)w * 16384;

    // ---- stage W^T hi/lo (128 rows x 256B) into padded smem ----
    for (int u = tid; u < 2048; u += 256) {
        int r = u >> 4, c = u & 15;
        *(uint4*)(smem + W_HI + r * RS + c * 16) = *(const uint4*)((const char*)wthi + r * 256 + c * 16);
        *(uint4*)(smem + W_LO + r * RS + c * 16) = *(const uint4*)((const char*)wtlo + r * 256 + c * 16);
    }

    // ---- convert A tile (64 x 128 fp32) to bf16 hi/lo ----
#pragma unroll
    for (int it = 0; it < 8; it++) {
        int idx = tid + (it << 8);           // 0..2047
        int row = idx >> 5;
        int kq = (idx & 31) << 2;
        float4 v = *(const float4*)(A + (size_t)row * 128 + kq);
        unsigned short h0, l0, h1, l1, h2, l2, h3, l3;
        split_bf16(v.x, h0, l0); split_bf16(v.y, h1, l1);
        split_bf16(v.z, h2, l2); split_bf16(v.w, h3, l3);
        ull hv = (ull)pack16(h0, h1) | ((ull)pack16(h2, h3) << 32);
        ull lv = (ull)pack16(l0, l1) | ((ull)pack16(l2, l3) << 32);
        *(ull*)(smem + A_HI + row * RS + kq * 2) = hv;
        *(ull*)(smem + A_LO + row * RS + kq * 2) = lv;
    }
    __syncthreads();

    const uint32_t sb = smem_u32(smem);
    const int warpM = (wid >> 2) << 5;     // 0 or 32
    const int warpN = (wid & 3) << 5;      // 0,32,64,96

    float acc[2][4][4];
#pragma unroll
    for (int mt = 0; mt < 2; mt++)
#pragma unroll
        for (int nt = 0; nt < 4; nt++)
#pragma unroll
            for (int i = 0; i < 4; i++) acc[mt][nt][i] = 0.0f;

    const int aRow = lane & 15;
    const uint32_t aK = (lane & 16) ? 16 : 0;
    const int bRow = lane & 7;
    const uint32_t bK = (lane & 8) ? 16 : 0;

#pragma unroll
    for (int kc = 0; kc < 8; kc++) {
        const uint32_t kb = kc * 32;
        uint32_t a_hi[2][4], a_lo[2][4];
#pragma unroll
        for (int mt = 0; mt < 2; mt++) {
            uint32_t off = (uint32_t)((warpM + mt * 16 + aRow) * RS) + kb + aK;
            ldsm4(a_hi[mt], sb + A_HI + off);
            ldsm4(a_lo[mt], sb + A_LO + off);
        }
#pragma unroll
        for (int nt = 0; nt < 4; nt++) {
            uint32_t off = (uint32_t)((warpN + nt * 8 + bRow) * RS) + kb + bK;
            uint32_t bh[2], bl[2];
            ldsm2(bh, sb + W_HI + off);
            ldsm2(bl, sb + W_LO + off);
#pragma unroll
            for (int mt = 0; mt < 2; mt++) {
                mma_bf16(acc[mt][nt], a_hi[mt], bh);
                mma_bf16(acc[mt][nt], a_hi[mt], bl);
                mma_bf16(acc[mt][nt], a_lo[mt], bh);
            }
        }
    }

    // ---- epilogue ----
    const int mrow = lane >> 2;
    const int ncol = (lane & 3) << 1;
#pragma unroll
    for (int mt = 0; mt < 2; mt++) {
#pragma unroll
        for (int nt = 0; nt < 4; nt++) {
            int row0 = warpM + mt * 16 + mrow;
            int col = warpN + nt * 8 + ncol;
            float2* p0 = (float2*)(C + (size_t)row0 * 128 + col);
            float2* p1 = (float2*)(C + (size_t)(row0 + 8) * 128 + col);
            float2 v0 = make_float2(acc[mt][nt][0], acc[mt][nt][1]);
            float2 v1 = make_float2(acc[mt][nt][2], acc[mt][nt][3]);
            if (accum) {
                float2 c0 = *p0, c1 = *p1;
                v0.x += c0.x; v0.y += c0.y;
                v1.x += c1.x; v1.y += c1.y;
            }
            *p0 = v0;
            *p1 = v1;
        }
    }
}

// ============================================================================
// Tensor product (unchanged): thread per (n, 4-ch group), f32x2 FMA.
// ============================================================================
__global__ __launch_bounds__(256) void tp_kernel(
    const float* __restrict__ aBase, const float* __restrict__ bBase,
    float* __restrict__ oBase)
{
    __shared__ ull s_cg[CG_TOTAL];
    for (int i = threadIdx.x; i < CG_TOTAL; i += 256) s_cg[i] = g_cgdup[i];
    __syncthreads();

    const int gid = blockIdx.x * 256 + threadIdx.x;
    const int kq = (gid & 31) << 2;
    const int n  = gid >> 5;

    constexpr int CUM[4] = {0, 1, 4, 9};
    constexpr int OFFL[4] = {0, 1 * NPTS * KCH, 4 * NPTS * KCH, 9 * NPTS * KCH};

    ull a[16][2];
#pragma unroll
    for (int l1 = 0; l1 < 4; l1++) {
        const int d1 = 2 * l1 + 1;
#pragma unroll
        for (int i = 0; i < d1; i++) {
            ulonglong2 v = *(const ulonglong2*)(aBase + OFFL[l1] + (n * d1 + i) * KCH + kq);
            a[CUM[l1] + i][0] = v.x; a[CUM[l1] + i][1] = v.y;
        }
    }

    ull acc[16][2];
#pragma unroll
    for (int r = 0; r < 16; r++) { acc[r][0] = 0ull; acc[r][1] = 0ull; }

    int cgi = 0;
#pragma unroll
    for (int l2 = 0; l2 < 4; l2++) {
        const int d2 = 2 * l2 + 1;
        ull b[7][2];
#pragma unroll
        for (int j = 0; j < d2; j++) {
            ulonglong2 v = *(const ulonglong2*)(bBase + OFFL[l2] + (n * d2 + j) * KCH + kq);
            b[j][0] = v.x; b[j][1] = v.y;
        }
#pragma unroll
        for (int l1 = 0; l1 < 4; l1++) {
            const int d1 = 2 * l1 + 1;
#pragma unroll
            for (int i = 0; i < d1; i++) {
#pragma unroll
                for (int j = 0; j < d2; j++) {
                    ull p0 = fmul2(a[CUM[l1] + i][0], b[j][0]);
                    ull p1 = fmul2(a[CUM[l1] + i][1], b[j][1]);
#pragma unroll
                    for (int l = 0; l < 4; l++) {
                        const int lo = (l1 > l2) ? (l1 - l2) : (l2 - l1);
                        if (l < lo || l > l1 + l2) continue;
                        const int dl = 2 * l + 1;
#pragma unroll
                        for (int m = 0; m < dl; m++) {
                            ull c = s_cg[cgi];
                            cgi++;
                            ffma2(acc[CUM[l] + m][0], c, p0);
                            ffma2(acc[CUM[l] + m][1], c, p1);
                        }
                    }
                }
            }
        }
    }

#pragma unroll
    for (int l = 0; l < 4; l++) {
        const int dl = 2 * l + 1;
#pragma unroll
        for (int m = 0; m < dl; m++) {
            ulonglong2 v;
            v.x = acc[CUM[l] + m][0]; v.y = acc[CUM[l] + m][1];
            *(ulonglong2*)(oBase + OFFL[l] + (n * dl + m) * KCH + kq) = v;
        }
    }
}

// ============================================================================
// launch
// ============================================================================
extern "C" void kernel_launch(void* const* d_in, const int* in_sizes, int n_in,
                              void* d_out, int out_size)
{
    const float* f[4] = {nullptr, nullptr, nullptr, nullptr};
    const float* mixer = nullptr;
    const float* iterw = nullptr;
    const float* cg = nullptr;

    for (int i = 0; i < n_in; i++) {
        const float* p = (const float*)d_in[i];
        switch (in_sizes[i]) {
            case 2097152:  f[0] = p; break;
            case 6291456:  f[1] = p; break;
            case 10485760: f[2] = p; break;
            case 14680064: f[3] = p; break;
            case 196608:   mixer = p; break;
            case 131072:   iterw = p; break;
            case 21952:    cg = p; break;
        }
    }
    if (!f[0] || !f[1] || !f[2] || !f[3] || !mixer || !iterw || !cg) {
        f[0] = (const float*)d_in[0]; f[1] = (const float*)d_in[1];
        f[2] = (const float*)d_in[2]; f[3] = (const float*)d_in[3];
        mixer = (const float*)d_in[4]; iterw = (const float*)d_in[5];
        cg = (const float*)d_in[6];
    }

    cudaFuncSetAttribute(tc_gemm_stage, cudaFuncAttributeMaxDynamicSharedMemorySize, GEMM_SMEM);

    float* out = (float*)d_out;
    float *m1, *m2, *tpb;
    __nv_bfloat16 *whi, *wlo;
    cudaGetSymbolAddress((void**)&m1, g_m1);
    cudaGetSymbolAddress((void**)&m2, g_m2);
    cudaGetSymbolAddress((void**)&tpb, g_tp);
    cudaGetSymbolAddress((void**)&whi, g_wthi);
    cudaGetSymbolAddress((void**)&wlo, g_wtlo);

    const size_t OFFL[4] = {0, (size_t)1 * NPTS * KCH, (size_t)4 * NPTS * KCH, (size_t)9 * NPTS * KCH};

    prep_cg_kernel<<<(CG_TOTAL + 255) / 256, 256>>>(cg);
    prep_w_kernel<<<NW, 256>>>(mixer, iterw);

    // mixer: mixed[0]->out, mixed[1]->m1, mixed[2]->m2 in ONE launch
    tc_gemm_stage<<<3 * 4096, 256, GEMM_SMEM>>>(
        f[0], f[1], f[2], f[3], out, m1, m2, whi, wlo, /*wbase=*/0, /*accum=*/0);

    // iteration 0: tp = TP(current, mixed1); current += tp @ iter_w[0]
    tp_kernel<<<NPTS * 32 / 256, 256>>>(out, m1, tpb);
    tc_gemm_stage<<<4096, 256, GEMM_SMEM>>>(
        tpb + OFFL[0], tpb + OFFL[1], tpb + OFFL[2], tpb + OFFL[3],
        out, out, out, whi, wlo, /*wbase=*/12, /*accum=*/1);

    // iteration 1: tp = TP(current, mixed2); current += tp @ iter_w[1]
    tp_kernel<<<NPTS * 32 / 256, 256>>>(out, m2, tpb);
    tc_gemm_stage<<<4096, 256, GEMM_SMEM>>>(
        tpb + OFFL[0], tpb + OFFL[1], tpb + OFFL[2], tpb + OFFL[3],
        out, out, out, whi, wlo, /*wbase=*/16, /*accum=*/1);
}